// round 7
// baseline (speedup 1.0000x reference)
#include <cuda_runtime.h>
#include <cuda_fp16.h>
#include <cstdint>

constexpr int B_  = 4;
constexpr int S_  = 2048;
constexpr int DM  = 1024;
constexpr int H_  = 16;
constexpr int DK_ = 64;
constexpr int DV_ = 64;
constexpr int ROWS = B_ * S_;
constexpr float SCALE2 = 11.54156003f;   // 8 * log2(e); folded into Q at proj time
constexpr float NEG    = -1000000000.0f;

// Pre-split inputs (hi/lo fp16)
__device__ __half g_ah[3][(size_t)ROWS * DM];
__device__ __half g_al[2][(size_t)ROWS * DM];
__device__ __half g_wh[3][(size_t)DM * DM];
__device__ __half g_wl[2][(size_t)DM * DM];

// Head-major projected tensors (Q pre-scaled by SCALE2)
__device__ __half g_qh_hi[(size_t)B_*H_*S_*DK_];
__device__ __half g_qh_lo[(size_t)B_*H_*S_*DK_];
__device__ __half g_kh_hi[(size_t)B_*H_*S_*DK_];
__device__ __half g_vh   [(size_t)B_*H_*S_*DV_];

// ---------------------------------------------------------------------------
// primitives
// ---------------------------------------------------------------------------
__device__ __forceinline__ uint32_t smaddr(const void* p) {
    return (uint32_t)__cvta_generic_to_shared(p);
}
__device__ __forceinline__ void ldsm_x4(uint32_t (&r)[4], uint32_t a) {
    asm volatile("ldmatrix.sync.aligned.m8n8.x4.shared.b16 {%0,%1,%2,%3}, [%4];"
                 : "=r"(r[0]), "=r"(r[1]), "=r"(r[2]), "=r"(r[3]) : "r"(a));
}
__device__ __forceinline__ void ldsm_x4_t(uint32_t (&r)[4], uint32_t a) {
    asm volatile("ldmatrix.sync.aligned.m8n8.x4.trans.shared.b16 {%0,%1,%2,%3}, [%4];"
                 : "=r"(r[0]), "=r"(r[1]), "=r"(r[2]), "=r"(r[3]) : "r"(a));
}
__device__ __forceinline__ void mma16816(float (&c)[4], const uint32_t (&a)[4],
                                         uint32_t b0, uint32_t b1) {
    asm volatile(
        "mma.sync.aligned.m16n8k16.row.col.f32.f16.f16.f32 "
        "{%0,%1,%2,%3}, {%4,%5,%6,%7}, {%8,%9}, {%0,%1,%2,%3};"
        : "+f"(c[0]), "+f"(c[1]), "+f"(c[2]), "+f"(c[3])
        : "r"(a[0]), "r"(a[1]), "r"(a[2]), "r"(a[3]), "r"(b0), "r"(b1));
}
__device__ __forceinline__ uint32_t packh2(float x, float y) {
    __half2 h = __floats2half2_rn(x, y);
    return *reinterpret_cast<uint32_t*>(&h);
}
__device__ __forceinline__ float ex2f(float x) {
    float y; asm("ex2.approx.ftz.f32 %0, %1;" : "=f"(y) : "f"(x)); return y;
}
__device__ __forceinline__ uint32_t ex2h2(float a, float b) {
    uint32_t h = packh2(a, b);
    uint32_t r; asm("ex2.approx.f16x2 %0, %1;" : "=r"(r) : "r"(h)); return r;
}
#define CP16(dst, src) asm volatile("cp.async.cg.shared.global [%0], [%1], 16;\n" :: "r"(dst), "l"(src))
#define CPC()          asm volatile("cp.async.commit_group;\n")
#define CPW(n)         asm volatile("cp.async.wait_group %0;\n" :: "n"(n))

// ---------------------------------------------------------------------------
// Kernel 0a/0b: pre-split fp32 -> (hi, lo) fp16
// ---------------------------------------------------------------------------
__global__ void split_a(const float* __restrict__ q, const float* __restrict__ k,
                        const float* __restrict__ v)
{
    const int z = blockIdx.y;
    const float* src = (z == 0) ? q : (z == 1) ? k : v;
    __half* hi = g_ah[z];
    __half* lo = (z < 2) ? g_al[z] : nullptr;
    size_t i = (size_t)blockIdx.x * blockDim.x + threadIdx.x;
    float4 vv = ((const float4*)src)[i];
    float f[4] = {vv.x, vv.y, vv.z, vv.w};
    __half h[4], l[4];
    #pragma unroll
    for (int e = 0; e < 4; e++) {
        h[e] = __float2half_rn(f[e]);
        l[e] = __float2half_rn(f[e] - __half2float(h[e]));
    }
    uint2 ph, pl;
    ph.x = (uint32_t)__half_as_ushort(h[0]) | ((uint32_t)__half_as_ushort(h[1]) << 16);
    ph.y = (uint32_t)__half_as_ushort(h[2]) | ((uint32_t)__half_as_ushort(h[3]) << 16);
    pl.x = (uint32_t)__half_as_ushort(l[0]) | ((uint32_t)__half_as_ushort(l[1]) << 16);
    pl.y = (uint32_t)__half_as_ushort(l[2]) | ((uint32_t)__half_as_ushort(l[3]) << 16);
    ((uint2*)hi)[i] = ph;
    if (lo) ((uint2*)lo)[i] = pl;
}
__global__ void split_w(const float* __restrict__ wq, const float* __restrict__ wk,
                        const float* __restrict__ wv)
{
    const int z = blockIdx.y;
    const float* src = (z == 0) ? wq : (z == 1) ? wk : wv;
    __half* hi = g_wh[z];
    __half* lo = (z < 2) ? g_wl[z] : nullptr;
    size_t i = (size_t)blockIdx.x * blockDim.x + threadIdx.x;
    float4 vv = ((const float4*)src)[i];
    float f[4] = {vv.x, vv.y, vv.z, vv.w};
    __half h[4], l[4];
    #pragma unroll
    for (int e = 0; e < 4; e++) {
        h[e] = __float2half_rn(f[e]);
        l[e] = __float2half_rn(f[e] - __half2float(h[e]));
    }
    uint2 ph, pl;
    ph.x = (uint32_t)__half_as_ushort(h[0]) | ((uint32_t)__half_as_ushort(h[1]) << 16);
    ph.y = (uint32_t)__half_as_ushort(h[2]) | ((uint32_t)__half_as_ushort(h[3]) << 16);
    pl.x = (uint32_t)__half_as_ushort(l[0]) | ((uint32_t)__half_as_ushort(l[1]) << 16);
    pl.y = (uint32_t)__half_as_ushort(l[2]) | ((uint32_t)__half_as_ushort(l[3]) << 16);
    ((uint2*)hi)[i] = ph;
    if (lo) ((uint2*)lo)[i] = pl;
}

// ---------------------------------------------------------------------------
// Kernel 1: projection GEMM. 128 threads (4 warps), tile 64x128, 4 CTAs/SM
// for barrier-domain desync. ldsm batched ahead of mma bursts.
// ---------------------------------------------------------------------------
struct ProjSmem {
    __half Ah[2][64][40];
    __half Al[2][64][40];
    __half Wh[2][32][136];
    __half Wl[2][32][136];
};   // 55,296 B

__global__ __launch_bounds__(128, 4) void proj_mma(
    const float* __restrict__ bq, const float* __restrict__ bk, const float* __restrict__ bv)
{
    extern __shared__ char smraw[];
    ProjSmem& S = *reinterpret_cast<ProjSmem*>(smraw);

    const int z = blockIdx.z;
    const __half* Agh = g_ah[z];
    const __half* Agl = (z < 2) ? g_al[z] : g_ah[z];
    const __half* Wgh = g_wh[z];
    const __half* Wgl = (z < 2) ? g_wl[z] : g_wh[z];
    const float* bias = (z == 0) ? bq : (z == 1) ? bk : bv;

    const int tid  = threadIdx.x;
    const int lane = tid & 31;
    const int warp = tid >> 5;              // 0..3
    const int wr = warp >> 1, wc = warp & 1;
    const int m_blk = blockIdx.y * 64;
    const int n_blk = blockIdx.x * 128;

    float acc[2][8][4];
    #pragma unroll
    for (int mt = 0; mt < 2; mt++)
        #pragma unroll
        for (int nt = 0; nt < 8; nt++)
            #pragma unroll
            for (int e = 0; e < 4; e++) acc[mt][nt][e] = 0.0f;

    auto load_tile = [&](int kt, int buf) {
        const int k0 = kt * 32;
        #pragma unroll
        for (int i = 0; i < 2; i++) {       // A: 64x32, 256 chunks / 128 thr
            int idx = tid * 2 + i;
            int ar = idx >> 2, ac = (idx & 3) * 8;
            size_t aoff = (size_t)(m_blk + ar) * DM + k0 + ac;
            CP16(smaddr(&S.Ah[buf][ar][ac]), Agh + aoff);
            if (z < 2) CP16(smaddr(&S.Al[buf][ar][ac]), Agl + aoff);
        }
        #pragma unroll
        for (int i = 0; i < 4; i++) {       // W: 32x128, 512 chunks / 128 thr
            int idx = tid * 4 + i;
            int wrow = idx >> 4, wcol = (idx & 15) * 8;
            size_t woff = (size_t)(k0 + wrow) * DM + n_blk + wcol;
            CP16(smaddr(&S.Wh[buf][wrow][wcol]), Wgh + woff);
            if (z < 2) CP16(smaddr(&S.Wl[buf][wrow][wcol]), Wgl + woff);
        }
        CPC();
    };

    load_tile(0, 0);

    for (int kt = 0; kt < DM / 32; kt++) {
        const int buf = kt & 1;
        CPW(0);
        __syncthreads();
        if (kt + 1 < DM / 32) load_tile(kt + 1, buf ^ 1);

        #pragma unroll
        for (int kc = 0; kc < 2; kc++) {
            // batched A ldsm
            uint32_t afh[2][4], afl[2][4];
            #pragma unroll
            for (int mt = 0; mt < 2; mt++) {
                int row = wr * 32 + mt * 16 + (lane & 15);
                int col = kc * 16 + (lane >> 4) * 8;
                ldsm_x4(afh[mt], smaddr(&S.Ah[buf][row][col]));
                if (z < 2) ldsm_x4(afl[mt], smaddr(&S.Al[buf][row][col]));
            }
            #pragma unroll
            for (int g = 0; g < 2; g++) {   // 2-ntp groups: batch ldsm, then mma burst
                uint32_t bh[2][4], bl[2][4];
                #pragma unroll
                for (int j = 0; j < 2; j++) {
                    int ntp = g * 2 + j;
                    int krow = kc * 16 + (lane & 15);
                    int ncol = wc * 64 + ntp * 16 + (lane >> 4) * 8;
                    ldsm_x4_t(bh[j], smaddr(&S.Wh[buf][krow][ncol]));
                    if (z < 2) ldsm_x4_t(bl[j], smaddr(&S.Wl[buf][krow][ncol]));
                }
                #pragma unroll
                for (int j = 0; j < 2; j++) {
                    int ntp = g * 2 + j;
                    #pragma unroll
                    for (int mt = 0; mt < 2; mt++) {
                        mma16816(acc[mt][2*ntp],   afh[mt], bh[j][0], bh[j][1]);
                        mma16816(acc[mt][2*ntp+1], afh[mt], bh[j][2], bh[j][3]);
                        if (z < 2) {
                            mma16816(acc[mt][2*ntp],   afh[mt], bl[j][0], bl[j][1]);
                            mma16816(acc[mt][2*ntp],   afl[mt], bh[j][0], bh[j][1]);
                            mma16816(acc[mt][2*ntp+1], afh[mt], bl[j][2], bl[j][3]);
                            mma16816(acc[mt][2*ntp+1], afl[mt], bh[j][2], bh[j][3]);
                        }
                    }
                }
            }
        }
    }

    // Epilogue: bias, head-major transpose; q: prescale + hi/lo, k: hi, v: plain
    #pragma unroll
    for (int mt = 0; mt < 2; mt++) {
        #pragma unroll
        for (int nt = 0; nt < 8; nt++) {
            int c = n_blk + wc * 64 + nt * 8 + 2 * (lane & 3);
            float b0 = bias[c], b1 = bias[c + 1];
            int hh = c >> 6, dd = c & 63;
            #pragma unroll
            for (int hf = 0; hf < 2; hf++) {
                int r = m_blk + wr * 32 + mt * 16 + (lane >> 2) + hf * 8;
                float v0 = acc[mt][nt][hf * 2 + 0] + b0;
                float v1 = acc[mt][nt][hf * 2 + 1] + b1;
                int batch = r >> 11, s = r & 2047;
                size_t idx = (((size_t)batch * H_ + hh) * S_ + s) * 64 + dd;
                if (z == 2) {
                    *(__half2*)&g_vh[idx] = __floats2half2_rn(v0, v1);
                } else if (z == 1) {
                    *(__half2*)&g_kh_hi[idx] = __floats2half2_rn(v0, v1);
                } else {
                    v0 *= SCALE2; v1 *= SCALE2;       // fold logit scaling into Q
                    __half h0 = __float2half_rn(v0), h1 = __float2half_rn(v1);
                    __half l0 = __float2half_rn(v0 - __half2float(h0));
                    __half l1 = __float2half_rn(v1 - __half2float(h1));
                    *(__half2*)&g_qh_hi[idx] = __halves2half2(h0, h1);
                    *(__half2*)&g_qh_lo[idx] = __halves2half2(l0, l1);
                }
            }
        }
    }
}

// ---------------------------------------------------------------------------
// Kernel 2: flash attention. Q-tile 128 (8 warps), K-tile 64, Q pre-scaled.
// ldsm batched in 2-ntp groups before mma bursts.
// ---------------------------------------------------------------------------
constexpr int KH_OFF = 0;
constexpr int VT_OFF = 18432;
constexpr int MS_OFF = 36864;
constexpr int QH_OFF = 0;          // alias over Kh region
constexpr int QL_OFF = 18432;      // alias over Vt region
constexpr int ATTN_SMEM = 37376;
constexpr int TSTRIDE = 4608;

__global__ __launch_bounds__(256, 2) void attn_mma(
    const float* __restrict__ qin,
    const int*   __restrict__ mask,
    float*       __restrict__ out)
{
    extern __shared__ char smraw[];
    __half* Kh = (__half*)(smraw + KH_OFF);
    __half* Vt = (__half*)(smraw + VT_OFF);
    int*    Ms = (int*)  (smraw + MS_OFF);
    __half* Qh = (__half*)(smraw + QH_OFF);
    __half* Ql = (__half*)(smraw + QL_OFF);

    const int tid  = threadIdx.x;
    const int lane = tid & 31;
    const int warp = tid >> 5;
    const int b  = blockIdx.z;
    const int h  = blockIdx.y;
    const int q0 = blockIdx.x * 128;

    const size_t head = ((size_t)b * H_ + h) * S_ * 64;
    const int* mrow = mask + (size_t)b * S_;
    const uint32_t ONESF = 0x3C003C00u;

    auto load_tile = [&](int kt, int buf) {
        const int kb = kt * 64;
        #pragma unroll
        for (int i = 0; i < 2; i++) {
            int idx = tid * 2 + i;
            int r = idx >> 3, c = (idx & 7) * 8;
            size_t g = head + (size_t)(kb + r) * 64 + c;
            CP16(smaddr(Kh + buf * TSTRIDE + r * 72 + c), g_kh_hi + g);
            CP16(smaddr(Vt + buf * TSTRIDE + r * 72 + c), g_vh    + g);
        }
        if (tid < 16) CP16(smaddr(Ms + buf * 64 + tid * 4), mrow + kb + tid * 4);
        CPC();
    };

    for (int i = tid; i < 1024; i += 256) {
        int r = i >> 3, c = (i & 7) * 8;
        size_t g = head + (size_t)(q0 + r) * 64 + c;
        CP16(smaddr(Qh + r * 72 + c), g_qh_hi + g);
        CP16(smaddr(Ql + r * 72 + c), g_qh_lo + g);
    }
    CPC(); CPW(0);
    __syncthreads();

    uint32_t qfh[4][4], qfl[4][4];
    const int m0 = warp * 16;
    #pragma unroll
    for (int kc = 0; kc < 4; kc++) {
        int row = m0 + (lane & 15);
        int col = kc * 16 + (lane >> 4) * 8;
        ldsm_x4(qfh[kc], smaddr(Qh + row * 72 + col));
        ldsm_x4(qfl[kc], smaddr(Ql + row * 72 + col));
    }
    __syncthreads();
    load_tile(0, 0);

    float m_i[2] = {-3.0e38f, -3.0e38f};
    float o[9][4];
    #pragma unroll
    for (int nt = 0; nt < 9; nt++)
        #pragma unroll
        for (int e = 0; e < 4; e++) o[nt][e] = 0.0f;

    for (int kt = 0; kt < S_ / 64; kt++) {
        const int buf = kt & 1;
        CPW(0);
        __syncthreads();
        if (kt + 1 < S_ / 64) load_tile(kt + 1, buf ^ 1);

        // S = Q K^T (2-product split); ldsm batched per 2-ntp group
        float s[8][4];
        #pragma unroll
        for (int nt = 0; nt < 8; nt++)
            #pragma unroll
            for (int e = 0; e < 4; e++) s[nt][e] = 0.0f;

        #pragma unroll
        for (int kc = 0; kc < 4; kc++) {
            #pragma unroll
            for (int g = 0; g < 2; g++) {
                uint32_t bh[2][4];
                #pragma unroll
                for (int j = 0; j < 2; j++) {
                    int ntp = g * 2 + j;
                    int row = ntp * 16 + (lane >> 4) * 8 + (lane & 7);
                    int col = kc * 16 + ((lane >> 3) & 1) * 8;
                    ldsm_x4(bh[j], smaddr(Kh + buf * TSTRIDE + row * 72 + col));
                }
                #pragma unroll
                for (int j = 0; j < 2; j++) {
                    int ntp = g * 2 + j;
                    mma16816(s[2*ntp],   qfh[kc], bh[j][0], bh[j][1]);
                    mma16816(s[2*ntp],   qfl[kc], bh[j][0], bh[j][1]);
                    mma16816(s[2*ntp+1], qfh[kc], bh[j][2], bh[j][3]);
                    mma16816(s[2*ntp+1], qfl[kc], bh[j][2], bh[j][3]);
                }
            }
        }

        // mask (Q already carries the SCALE2 factor)
        #pragma unroll
        for (int nt = 0; nt < 8; nt++) {
            int c0 = nt * 8 + 2 * (lane & 3);
            bool d0 = (Ms[buf * 64 + c0] == 0), d1 = (Ms[buf * 64 + c0 + 1] == 0);
            s[nt][0] = d0 ? NEG : s[nt][0];
            s[nt][1] = d1 ? NEG : s[nt][1];
            s[nt][2] = d0 ? NEG : s[nt][2];
            s[nt][3] = d1 ? NEG : s[nt][3];
        }

        // online softmax (base-2)
        float mx0 = -3.0e38f, mx1 = -3.0e38f;
        #pragma unroll
        for (int nt = 0; nt < 8; nt++) {
            mx0 = fmaxf(mx0, fmaxf(s[nt][0], s[nt][1]));
            mx1 = fmaxf(mx1, fmaxf(s[nt][2], s[nt][3]));
        }
        mx0 = fmaxf(mx0, __shfl_xor_sync(0xffffffffu, mx0, 1));
        mx0 = fmaxf(mx0, __shfl_xor_sync(0xffffffffu, mx0, 2));
        mx1 = fmaxf(mx1, __shfl_xor_sync(0xffffffffu, mx1, 1));
        mx1 = fmaxf(mx1, __shfl_xor_sync(0xffffffffu, mx1, 2));
        float mn0 = fmaxf(fmaxf(m_i[0], mx0), -1.0e8f);
        float mn1 = fmaxf(fmaxf(m_i[1], mx1), -1.0e8f);
        float sc0 = ex2f(m_i[0] - mn0), sc1 = ex2f(m_i[1] - mn1);
        m_i[0] = mn0; m_i[1] = mn1;

        uint32_t p[8][2];
        #pragma unroll
        for (int nt = 0; nt < 8; nt++) {
            p[nt][0] = ex2h2(s[nt][0] - mn0, s[nt][1] - mn0);
            p[nt][1] = ex2h2(s[nt][2] - mn1, s[nt][3] - mn1);
        }

        #pragma unroll
        for (int nt = 0; nt < 9; nt++) {
            o[nt][0] *= sc0; o[nt][1] *= sc0;
            o[nt][2] *= sc1; o[nt][3] *= sc1;
        }

        // O += P V ; denom += P 1   (ldsm batched per 2-ntp group)
        #pragma unroll
        for (int kc = 0; kc < 4; kc++) {
            uint32_t a[4] = { p[2*kc][0], p[2*kc][1], p[2*kc+1][0], p[2*kc+1][1] };
            #pragma unroll
            for (int g = 0; g < 2; g++) {
                uint32_t bv[2][4];
                #pragma unroll
                for (int j = 0; j < 2; j++) {
                    int ntp = g * 2 + j;
                    int row = kc * 16 + (lane & 15);
                    int col = ntp * 16 + (lane >> 4) * 8;
                    ldsm_x4_t(bv[j], smaddr(Vt + buf * TSTRIDE + row * 72 + col));
                }
                #pragma unroll
                for (int j = 0; j < 2; j++) {
                    int ntp = g * 2 + j;
                    mma16816(o[2*ntp],   a, bv[j][0], bv[j][1]);
                    mma16816(o[2*ntp+1], a, bv[j][2], bv[j][3]);
                }
            }
            mma16816(o[8], a, ONESF, ONESF);
        }
    }

    // Epilogue: /l, residual add, write (b, s, h*64+d)
    float inv0 = 1.0f / o[8][0], inv1 = 1.0f / o[8][2];
    int r0 = q0 + warp * 16 + (lane >> 2);
    int r1 = r0 + 8;
    #pragma unroll
    for (int nt = 0; nt < 8; nt++) {
        int c = h * 64 + nt * 8 + 2 * (lane & 3);
        size_t i0 = ((size_t)b * S_ + r0) * (H_ * DV_) + c;
        size_t i1 = ((size_t)b * S_ + r1) * (H_ * DV_) + c;
        float2 q0v = *(const float2*)(qin + i0);
        float2 q1v = *(const float2*)(qin + i1);
        float2 o0, o1;
        o0.x = o[nt][0] * inv0 + q0v.x;
        o0.y = o[nt][1] * inv0 + q0v.y;
        o1.x = o[nt][2] * inv1 + q1v.x;
        o1.y = o[nt][3] * inv1 + q1v.y;
        *(float2*)(out + i0) = o0;
        *(float2*)(out + i1) = o1;
    }
}

extern "C" void kernel_launch(void* const* d_in, const int* in_sizes, int n_in,
                              void* d_out, int out_size)
{
    (void)in_sizes; (void)n_in; (void)out_size;
    const float* q    = (const float*)d_in[0];
    const float* k    = (const float*)d_in[1];
    const float* v    = (const float*)d_in[2];
    const int*   mask = (const int*)  d_in[3];
    const float* wq   = (const float*)d_in[4];
    const float* bq   = (const float*)d_in[5];
    const float* wk   = (const float*)d_in[6];
    const float* bk   = (const float*)d_in[7];
    const float* wv   = (const float*)d_in[8];
    const float* bv   = (const float*)d_in[9];
    float* out = (float*)d_out;

    static bool attr_set = false;
    if (!attr_set) {
        cudaFuncSetAttribute(proj_mma, cudaFuncAttributeMaxDynamicSharedMemorySize,
                             (int)sizeof(ProjSmem));
        attr_set = true;
    }

    dim3 sag((ROWS * DM / 4) / 256, 3);
    split_a<<<sag, 256>>>(q, k, v);
    dim3 swg((DM * DM / 4) / 256, 3);
    split_w<<<swg, 256>>>(wq, wk, wv);

    dim3 pg(DM / 128, ROWS / 64, 3);      // (8, 128, 3)
    proj_mma<<<pg, 128, sizeof(ProjSmem)>>>(bq, bk, bv);

    dim3 ag(S_ / 128, H_, B_);            // (16, 16, 4)
    attn_mma<<<ag, 256, ATTN_SMEM>>>(q, mask, out);
}

// round 8
// speedup vs baseline: 1.1873x; 1.1873x over previous
#include <cuda_runtime.h>
#include <cuda_fp16.h>
#include <cstdint>

constexpr int B_  = 4;
constexpr int S_  = 2048;
constexpr int DM  = 1024;
constexpr int H_  = 16;
constexpr int DK_ = 64;
constexpr int DV_ = 64;
constexpr int ROWS = B_ * S_;
constexpr float SCALE2 = 11.54156003f;   // 8 * log2(e); folded into Q at proj time
constexpr float NEG    = -1000000000.0f;

// Pre-split inputs (hi/lo fp16)
__device__ __half g_ah[3][(size_t)ROWS * DM];
__device__ __half g_al[2][(size_t)ROWS * DM];
__device__ __half g_wh[3][(size_t)DM * DM];
__device__ __half g_wl[2][(size_t)DM * DM];

// Head-major projected tensors (Q pre-scaled by SCALE2)
__device__ __half g_qh_hi[(size_t)B_*H_*S_*DK_];
__device__ __half g_qh_lo[(size_t)B_*H_*S_*DK_];
__device__ __half g_kh_hi[(size_t)B_*H_*S_*DK_];
__device__ __half g_vh   [(size_t)B_*H_*S_*DV_];

// Mask compaction
__device__ int    g_idx[B_][S_];
__device__ int    g_cnt[B_];
__device__ __half g_kc[(size_t)B_*H_*S_*DK_];   // compacted K (hi)
__device__ __half g_vc[(size_t)B_*H_*S_*DV_];   // compacted V

// ---------------------------------------------------------------------------
// primitives
// ---------------------------------------------------------------------------
__device__ __forceinline__ uint32_t smaddr(const void* p) {
    return (uint32_t)__cvta_generic_to_shared(p);
}
__device__ __forceinline__ void ldsm_x4(uint32_t (&r)[4], uint32_t a) {
    asm volatile("ldmatrix.sync.aligned.m8n8.x4.shared.b16 {%0,%1,%2,%3}, [%4];"
                 : "=r"(r[0]), "=r"(r[1]), "=r"(r[2]), "=r"(r[3]) : "r"(a));
}
__device__ __forceinline__ void ldsm_x4_t(uint32_t (&r)[4], uint32_t a) {
    asm volatile("ldmatrix.sync.aligned.m8n8.x4.trans.shared.b16 {%0,%1,%2,%3}, [%4];"
                 : "=r"(r[0]), "=r"(r[1]), "=r"(r[2]), "=r"(r[3]) : "r"(a));
}
__device__ __forceinline__ void mma16816(float (&c)[4], const uint32_t (&a)[4],
                                         uint32_t b0, uint32_t b1) {
    asm volatile(
        "mma.sync.aligned.m16n8k16.row.col.f32.f16.f16.f32 "
        "{%0,%1,%2,%3}, {%4,%5,%6,%7}, {%8,%9}, {%0,%1,%2,%3};"
        : "+f"(c[0]), "+f"(c[1]), "+f"(c[2]), "+f"(c[3])
        : "r"(a[0]), "r"(a[1]), "r"(a[2]), "r"(a[3]), "r"(b0), "r"(b1));
}
__device__ __forceinline__ uint32_t packh2(float x, float y) {
    __half2 h = __floats2half2_rn(x, y);
    return *reinterpret_cast<uint32_t*>(&h);
}
__device__ __forceinline__ float ex2f(float x) {
    float y; asm("ex2.approx.ftz.f32 %0, %1;" : "=f"(y) : "f"(x)); return y;
}
__device__ __forceinline__ uint32_t ex2h2(float a, float b) {
    uint32_t h = packh2(a, b);
    uint32_t r; asm("ex2.approx.f16x2 %0, %1;" : "=r"(r) : "r"(h)); return r;
}
#define CP16(dst, src) asm volatile("cp.async.cg.shared.global [%0], [%1], 16;\n" :: "r"(dst), "l"(src))
#define CPC()          asm volatile("cp.async.commit_group;\n")
#define CPW(n)         asm volatile("cp.async.wait_group %0;\n" :: "n"(n))

// ---------------------------------------------------------------------------
// Kernel 0a/0b: pre-split fp32 -> (hi, lo) fp16
// ---------------------------------------------------------------------------
__global__ void split_a(const float* __restrict__ q, const float* __restrict__ k,
                        const float* __restrict__ v)
{
    const int z = blockIdx.y;
    const float* src = (z == 0) ? q : (z == 1) ? k : v;
    __half* hi = g_ah[z];
    __half* lo = (z < 2) ? g_al[z] : nullptr;
    size_t i = (size_t)blockIdx.x * blockDim.x + threadIdx.x;
    float4 vv = ((const float4*)src)[i];
    float f[4] = {vv.x, vv.y, vv.z, vv.w};
    __half h[4], l[4];
    #pragma unroll
    for (int e = 0; e < 4; e++) {
        h[e] = __float2half_rn(f[e]);
        l[e] = __float2half_rn(f[e] - __half2float(h[e]));
    }
    uint2 ph, pl;
    ph.x = (uint32_t)__half_as_ushort(h[0]) | ((uint32_t)__half_as_ushort(h[1]) << 16);
    ph.y = (uint32_t)__half_as_ushort(h[2]) | ((uint32_t)__half_as_ushort(h[3]) << 16);
    pl.x = (uint32_t)__half_as_ushort(l[0]) | ((uint32_t)__half_as_ushort(l[1]) << 16);
    pl.y = (uint32_t)__half_as_ushort(l[2]) | ((uint32_t)__half_as_ushort(l[3]) << 16);
    ((uint2*)hi)[i] = ph;
    if (lo) ((uint2*)lo)[i] = pl;
}
__global__ void split_w(const float* __restrict__ wq, const float* __restrict__ wk,
                        const float* __restrict__ wv)
{
    const int z = blockIdx.y;
    const float* src = (z == 0) ? wq : (z == 1) ? wk : wv;
    __half* hi = g_wh[z];
    __half* lo = (z < 2) ? g_wl[z] : nullptr;
    size_t i = (size_t)blockIdx.x * blockDim.x + threadIdx.x;
    float4 vv = ((const float4*)src)[i];
    float f[4] = {vv.x, vv.y, vv.z, vv.w};
    __half h[4], l[4];
    #pragma unroll
    for (int e = 0; e < 4; e++) {
        h[e] = __float2half_rn(f[e]);
        l[e] = __float2half_rn(f[e] - __half2float(h[e]));
    }
    uint2 ph, pl;
    ph.x = (uint32_t)__half_as_ushort(h[0]) | ((uint32_t)__half_as_ushort(h[1]) << 16);
    ph.y = (uint32_t)__half_as_ushort(h[2]) | ((uint32_t)__half_as_ushort(h[3]) << 16);
    pl.x = (uint32_t)__half_as_ushort(l[0]) | ((uint32_t)__half_as_ushort(l[1]) << 16);
    pl.y = (uint32_t)__half_as_ushort(l[2]) | ((uint32_t)__half_as_ushort(l[3]) << 16);
    ((uint2*)hi)[i] = ph;
    if (lo) ((uint2*)lo)[i] = pl;
}

// ---------------------------------------------------------------------------
// Kernel 0c: mask scan — per-batch index list of unmasked positions
// ---------------------------------------------------------------------------
__global__ void mask_scan(const int* __restrict__ mask)
{
    const int bw   = threadIdx.x >> 5;    // batch = warp
    const int lane = threadIdx.x & 31;
    const int* mrow = mask + (size_t)bw * S_;
    int running = 0;
    for (int s0 = 0; s0 < S_; s0 += 32) {
        int m = mrow[s0 + lane];
        unsigned bal = __ballot_sync(0xffffffffu, m != 0);
        int pre = __popc(bal & ((1u << lane) - 1u));
        if (m != 0) g_idx[bw][running + pre] = s0 + lane;
        running += __popc(bal);
    }
    if (lane == 0) g_cnt[bw] = running;
    int npad = (running + 63) & ~63;
    for (int j = running + lane; j < npad; j += 32) g_idx[bw][j] = 0;
}

// ---------------------------------------------------------------------------
// Kernel 0d: gather compacted K/V (row-granular, 128B rows)
// ---------------------------------------------------------------------------
__global__ void compact_kv()
{
    const int b = blockIdx.z;
    const int h = blockIdx.y;
    const int jbase = blockIdx.x * 128;
    const int npad = (g_cnt[b] + 63) & ~63;
    const size_t head = ((size_t)b * H_ + h) * S_ * 64;
    const int tid = threadIdx.x;
    const int rsub = tid >> 3;            // 0..15
    const int c    = (tid & 7) * 8;       // half offset in row
    #pragma unroll
    for (int it = 0; it < 8; it++) {
        int j = jbase + it * 16 + rsub;
        if (j < npad) {
            int src = g_idx[b][j];
            *(uint4*)(g_kc + head + (size_t)j * 64 + c) =
                *(const uint4*)(g_kh_hi + head + (size_t)src * 64 + c);
            *(uint4*)(g_vc + head + (size_t)j * 64 + c) =
                *(const uint4*)(g_vh + head + (size_t)src * 64 + c);
        }
    }
}

// ---------------------------------------------------------------------------
// Kernel 1: projection GEMM (as R7: 4 warps, 64x128 tile, 4 CTAs/SM)
// ---------------------------------------------------------------------------
struct ProjSmem {
    __half Ah[2][64][40];
    __half Al[2][64][40];
    __half Wh[2][32][136];
    __half Wl[2][32][136];
};

__global__ __launch_bounds__(128, 4) void proj_mma(
    const float* __restrict__ bq, const float* __restrict__ bk, const float* __restrict__ bv)
{
    extern __shared__ char smraw[];
    ProjSmem& S = *reinterpret_cast<ProjSmem*>(smraw);

    const int z = blockIdx.z;
    const __half* Agh = g_ah[z];
    const __half* Agl = (z < 2) ? g_al[z] : g_ah[z];
    const __half* Wgh = g_wh[z];
    const __half* Wgl = (z < 2) ? g_wl[z] : g_wh[z];
    const float* bias = (z == 0) ? bq : (z == 1) ? bk : bv;

    const int tid  = threadIdx.x;
    const int lane = tid & 31;
    const int warp = tid >> 5;
    const int wr = warp >> 1, wc = warp & 1;
    const int m_blk = blockIdx.y * 64;
    const int n_blk = blockIdx.x * 128;

    float acc[2][8][4];
    #pragma unroll
    for (int mt = 0; mt < 2; mt++)
        #pragma unroll
        for (int nt = 0; nt < 8; nt++)
            #pragma unroll
            for (int e = 0; e < 4; e++) acc[mt][nt][e] = 0.0f;

    auto load_tile = [&](int kt, int buf) {
        const int k0 = kt * 32;
        #pragma unroll
        for (int i = 0; i < 2; i++) {
            int idx = tid * 2 + i;
            int ar = idx >> 2, ac = (idx & 3) * 8;
            size_t aoff = (size_t)(m_blk + ar) * DM + k0 + ac;
            CP16(smaddr(&S.Ah[buf][ar][ac]), Agh + aoff);
            if (z < 2) CP16(smaddr(&S.Al[buf][ar][ac]), Agl + aoff);
        }
        #pragma unroll
        for (int i = 0; i < 4; i++) {
            int idx = tid * 4 + i;
            int wrow = idx >> 4, wcol = (idx & 15) * 8;
            size_t woff = (size_t)(k0 + wrow) * DM + n_blk + wcol;
            CP16(smaddr(&S.Wh[buf][wrow][wcol]), Wgh + woff);
            if (z < 2) CP16(smaddr(&S.Wl[buf][wrow][wcol]), Wgl + woff);
        }
        CPC();
    };

    load_tile(0, 0);

    for (int kt = 0; kt < DM / 32; kt++) {
        const int buf = kt & 1;
        CPW(0);
        __syncthreads();
        if (kt + 1 < DM / 32) load_tile(kt + 1, buf ^ 1);

        #pragma unroll
        for (int kc = 0; kc < 2; kc++) {
            uint32_t afh[2][4], afl[2][4];
            #pragma unroll
            for (int mt = 0; mt < 2; mt++) {
                int row = wr * 32 + mt * 16 + (lane & 15);
                int col = kc * 16 + (lane >> 4) * 8;
                ldsm_x4(afh[mt], smaddr(&S.Ah[buf][row][col]));
                if (z < 2) ldsm_x4(afl[mt], smaddr(&S.Al[buf][row][col]));
            }
            #pragma unroll
            for (int g = 0; g < 2; g++) {
                uint32_t bh[2][4], bl[2][4];
                #pragma unroll
                for (int j = 0; j < 2; j++) {
                    int ntp = g * 2 + j;
                    int krow = kc * 16 + (lane & 15);
                    int ncol = wc * 64 + ntp * 16 + (lane >> 4) * 8;
                    ldsm_x4_t(bh[j], smaddr(&S.Wh[buf][krow][ncol]));
                    if (z < 2) ldsm_x4_t(bl[j], smaddr(&S.Wl[buf][krow][ncol]));
                }
                #pragma unroll
                for (int j = 0; j < 2; j++) {
                    int ntp = g * 2 + j;
                    #pragma unroll
                    for (int mt = 0; mt < 2; mt++) {
                        mma16816(acc[mt][2*ntp],   afh[mt], bh[j][0], bh[j][1]);
                        mma16816(acc[mt][2*ntp+1], afh[mt], bh[j][2], bh[j][3]);
                        if (z < 2) {
                            mma16816(acc[mt][2*ntp],   afh[mt], bl[j][0], bl[j][1]);
                            mma16816(acc[mt][2*ntp],   afl[mt], bh[j][0], bh[j][1]);
                            mma16816(acc[mt][2*ntp+1], afh[mt], bl[j][2], bl[j][3]);
                            mma16816(acc[mt][2*ntp+1], afl[mt], bh[j][2], bh[j][3]);
                        }
                    }
                }
            }
        }
    }

    #pragma unroll
    for (int mt = 0; mt < 2; mt++) {
        #pragma unroll
        for (int nt = 0; nt < 8; nt++) {
            int c = n_blk + wc * 64 + nt * 8 + 2 * (lane & 3);
            float b0 = bias[c], b1 = bias[c + 1];
            int hh = c >> 6, dd = c & 63;
            #pragma unroll
            for (int hf = 0; hf < 2; hf++) {
                int r = m_blk + wr * 32 + mt * 16 + (lane >> 2) + hf * 8;
                float v0 = acc[mt][nt][hf * 2 + 0] + b0;
                float v1 = acc[mt][nt][hf * 2 + 1] + b1;
                int batch = r >> 11, s = r & 2047;
                size_t idx = (((size_t)batch * H_ + hh) * S_ + s) * 64 + dd;
                if (z == 2) {
                    *(__half2*)&g_vh[idx] = __floats2half2_rn(v0, v1);
                } else if (z == 1) {
                    *(__half2*)&g_kh_hi[idx] = __floats2half2_rn(v0, v1);
                } else {
                    v0 *= SCALE2; v1 *= SCALE2;
                    __half h0 = __float2half_rn(v0), h1 = __float2half_rn(v1);
                    __half l0 = __float2half_rn(v0 - __half2float(h0));
                    __half l1 = __float2half_rn(v1 - __half2float(h1));
                    *(__half2*)&g_qh_hi[idx] = __halves2half2(h0, h1);
                    *(__half2*)&g_qh_lo[idx] = __halves2half2(l0, l1);
                }
            }
        }
    }
}

// ---------------------------------------------------------------------------
// Kernel 2: flash attention over COMPACTED keys. Q-tile 128, K-tile 64.
// Tail masking by register compare (col >= n_cnt); no mask smem.
// ---------------------------------------------------------------------------
constexpr int KH_OFF = 0;
constexpr int VT_OFF = 18432;
constexpr int QH_OFF = 0;          // alias over Kh region
constexpr int QL_OFF = 18432;      // alias over Vt region
constexpr int ATTN_SMEM = 36864;
constexpr int TSTRIDE = 4608;

__global__ __launch_bounds__(256, 2) void attn_mma(
    const float* __restrict__ qin,
    float*       __restrict__ out)
{
    extern __shared__ char smraw[];
    __half* Kh = (__half*)(smraw + KH_OFF);
    __half* Vt = (__half*)(smraw + VT_OFF);
    __half* Qh = (__half*)(smraw + QH_OFF);
    __half* Ql = (__half*)(smraw + QL_OFF);

    const int tid  = threadIdx.x;
    const int lane = tid & 31;
    const int warp = tid >> 5;
    const int b  = blockIdx.z;
    const int h  = blockIdx.y;
    const int q0 = blockIdx.x * 128;

    const size_t head = ((size_t)b * H_ + h) * S_ * 64;
    const int n_cnt = g_cnt[b];
    const int ntile = (n_cnt + 63) >> 6;
    const uint32_t ONESF = 0x3C003C00u;

    auto load_tile = [&](int kt, int buf) {
        const int kb = kt * 64;
        #pragma unroll
        for (int i = 0; i < 2; i++) {
            int idx = tid * 2 + i;
            int r = idx >> 3, c = (idx & 7) * 8;
            size_t g = head + (size_t)(kb + r) * 64 + c;
            CP16(smaddr(Kh + buf * TSTRIDE + r * 72 + c), g_kc + g);
            CP16(smaddr(Vt + buf * TSTRIDE + r * 72 + c), g_vc + g);
        }
        CPC();
    };

    for (int i = tid; i < 1024; i += 256) {
        int r = i >> 3, c = (i & 7) * 8;
        size_t g = head + (size_t)(q0 + r) * 64 + c;
        CP16(smaddr(Qh + r * 72 + c), g_qh_hi + g);
        CP16(smaddr(Ql + r * 72 + c), g_qh_lo + g);
    }
    CPC(); CPW(0);
    __syncthreads();

    uint32_t qfh[4][4], qfl[4][4];
    const int m0 = warp * 16;
    #pragma unroll
    for (int kc = 0; kc < 4; kc++) {
        int row = m0 + (lane & 15);
        int col = kc * 16 + (lane >> 4) * 8;
        ldsm_x4(qfh[kc], smaddr(Qh + row * 72 + col));
        ldsm_x4(qfl[kc], smaddr(Ql + row * 72 + col));
    }
    __syncthreads();
    load_tile(0, 0);

    float m_i[2] = {-3.0e38f, -3.0e38f};
    float o[9][4];
    #pragma unroll
    for (int nt = 0; nt < 9; nt++)
        #pragma unroll
        for (int e = 0; e < 4; e++) o[nt][e] = 0.0f;

    for (int kt = 0; kt < ntile; kt++) {
        const int buf = kt & 1;
        CPW(0);
        __syncthreads();
        if (kt + 1 < ntile) load_tile(kt + 1, buf ^ 1);

        float s[8][4];
        #pragma unroll
        for (int nt = 0; nt < 8; nt++)
            #pragma unroll
            for (int e = 0; e < 4; e++) s[nt][e] = 0.0f;

        #pragma unroll
        for (int kc = 0; kc < 4; kc++) {
            #pragma unroll
            for (int g = 0; g < 2; g++) {
                uint32_t bh[2][4];
                #pragma unroll
                for (int j = 0; j < 2; j++) {
                    int ntp = g * 2 + j;
                    int row = ntp * 16 + (lane >> 4) * 8 + (lane & 7);
                    int col = kc * 16 + ((lane >> 3) & 1) * 8;
                    ldsm_x4(bh[j], smaddr(Kh + buf * TSTRIDE + row * 72 + col));
                }
                #pragma unroll
                for (int j = 0; j < 2; j++) {
                    int ntp = g * 2 + j;
                    mma16816(s[2*ntp],   qfh[kc], bh[j][0], bh[j][1]);
                    mma16816(s[2*ntp],   qfl[kc], bh[j][0], bh[j][1]);
                    mma16816(s[2*ntp+1], qfh[kc], bh[j][2], bh[j][3]);
                    mma16816(s[2*ntp+1], qfl[kc], bh[j][2], bh[j][3]);
                }
            }
        }

        // tail masking: compacted col >= n_cnt is padding
        const int cbase = kt * 64 + 2 * (lane & 3);
        #pragma unroll
        for (int nt = 0; nt < 8; nt++) {
            int c0 = cbase + nt * 8;
            if (c0 >= n_cnt)     { s[nt][0] = NEG; s[nt][2] = NEG; }
            if (c0 + 1 >= n_cnt) { s[nt][1] = NEG; s[nt][3] = NEG; }
        }

        float mx0 = -3.0e38f, mx1 = -3.0e38f;
        #pragma unroll
        for (int nt = 0; nt < 8; nt++) {
            mx0 = fmaxf(mx0, fmaxf(s[nt][0], s[nt][1]));
            mx1 = fmaxf(mx1, fmaxf(s[nt][2], s[nt][3]));
        }
        mx0 = fmaxf(mx0, __shfl_xor_sync(0xffffffffu, mx0, 1));
        mx0 = fmaxf(mx0, __shfl_xor_sync(0xffffffffu, mx0, 2));
        mx1 = fmaxf(mx1, __shfl_xor_sync(0xffffffffu, mx1, 1));
        mx1 = fmaxf(mx1, __shfl_xor_sync(0xffffffffu, mx1, 2));
        float mn0 = fmaxf(fmaxf(m_i[0], mx0), -1.0e8f);
        float mn1 = fmaxf(fmaxf(m_i[1], mx1), -1.0e8f);
        float sc0 = ex2f(m_i[0] - mn0), sc1 = ex2f(m_i[1] - mn1);
        m_i[0] = mn0; m_i[1] = mn1;

        uint32_t p[8][2];
        #pragma unroll
        for (int nt = 0; nt < 8; nt++) {
            p[nt][0] = ex2h2(s[nt][0] - mn0, s[nt][1] - mn0);
            p[nt][1] = ex2h2(s[nt][2] - mn1, s[nt][3] - mn1);
        }

        #pragma unroll
        for (int nt = 0; nt < 9; nt++) {
            o[nt][0] *= sc0; o[nt][1] *= sc0;
            o[nt][2] *= sc1; o[nt][3] *= sc1;
        }

        #pragma unroll
        for (int kc = 0; kc < 4; kc++) {
            uint32_t a[4] = { p[2*kc][0], p[2*kc][1], p[2*kc+1][0], p[2*kc+1][1] };
            #pragma unroll
            for (int g = 0; g < 2; g++) {
                uint32_t bv[2][4];
                #pragma unroll
                for (int j = 0; j < 2; j++) {
                    int ntp = g * 2 + j;
                    int row = kc * 16 + (lane & 15);
                    int col = ntp * 16 + (lane >> 4) * 8;
                    ldsm_x4_t(bv[j], smaddr(Vt + buf * TSTRIDE + row * 72 + col));
                }
                #pragma unroll
                for (int j = 0; j < 2; j++) {
                    int ntp = g * 2 + j;
                    mma16816(o[2*ntp],   a, bv[j][0], bv[j][1]);
                    mma16816(o[2*ntp+1], a, bv[j][2], bv[j][3]);
                }
            }
            mma16816(o[8], a, ONESF, ONESF);
        }
    }

    float inv0 = 1.0f / o[8][0], inv1 = 1.0f / o[8][2];
    int r0 = q0 + warp * 16 + (lane >> 2);
    int r1 = r0 + 8;
    #pragma unroll
    for (int nt = 0; nt < 8; nt++) {
        int c = h * 64 + nt * 8 + 2 * (lane & 3);
        size_t i0 = ((size_t)b * S_ + r0) * (H_ * DV_) + c;
        size_t i1 = ((size_t)b * S_ + r1) * (H_ * DV_) + c;
        float2 q0v = *(const float2*)(qin + i0);
        float2 q1v = *(const float2*)(qin + i1);
        float2 o0, o1;
        o0.x = o[nt][0] * inv0 + q0v.x;
        o0.y = o[nt][1] * inv0 + q0v.y;
        o1.x = o[nt][2] * inv1 + q1v.x;
        o1.y = o[nt][3] * inv1 + q1v.y;
        *(float2*)(out + i0) = o0;
        *(float2*)(out + i1) = o1;
    }
}

extern "C" void kernel_launch(void* const* d_in, const int* in_sizes, int n_in,
                              void* d_out, int out_size)
{
    (void)in_sizes; (void)n_in; (void)out_size;
    const float* q    = (const float*)d_in[0];
    const float* k    = (const float*)d_in[1];
    const float* v    = (const float*)d_in[2];
    const int*   mask = (const int*)  d_in[3];
    const float* wq   = (const float*)d_in[4];
    const float* bq   = (const float*)d_in[5];
    const float* wk   = (const float*)d_in[6];
    const float* bk   = (const float*)d_in[7];
    const float* wv   = (const float*)d_in[8];
    const float* bv   = (const float*)d_in[9];
    float* out = (float*)d_out;

    static bool attr_set = false;
    if (!attr_set) {
        cudaFuncSetAttribute(proj_mma, cudaFuncAttributeMaxDynamicSharedMemorySize,
                             (int)sizeof(ProjSmem));
        attr_set = true;
    }

    dim3 sag((ROWS * DM / 4) / 256, 3);
    split_a<<<sag, 256>>>(q, k, v);
    dim3 swg((DM * DM / 4) / 256, 3);
    split_w<<<swg, 256>>>(wq, wk, wv);
    mask_scan<<<1, 128>>>(mask);

    dim3 pg(DM / 128, ROWS / 64, 3);
    proj_mma<<<pg, 128, sizeof(ProjSmem)>>>(bq, bk, bv);

    dim3 cg(S_ / 128, H_, B_);
    compact_kv<<<cg, 128>>>();

    dim3 ag(S_ / 128, H_, B_);
    attn_mma<<<ag, 256, ATTN_SMEM>>>(q, out);
}

// round 9
// speedup vs baseline: 1.4975x; 1.2613x over previous
#include <cuda_runtime.h>
#include <cuda_fp16.h>
#include <cstdint>

constexpr int B_  = 4;
constexpr int S_  = 2048;
constexpr int DM  = 1024;
constexpr int H_  = 16;
constexpr int DK_ = 64;
constexpr int DV_ = 64;
constexpr int ROWS = B_ * S_;
constexpr float SCALE2 = 11.54156003f;   // 8 * log2(e); folded into Q at proj time
constexpr float NEG    = -1000000000.0f;

// Pre-split inputs (hi/lo fp16)
__device__ __half g_ah[3][(size_t)ROWS * DM];
__device__ __half g_al[2][(size_t)ROWS * DM];
__device__ __half g_wh[3][(size_t)DM * DM];
__device__ __half g_wl[2][(size_t)DM * DM];

// Head-major projected tensors (Q pre-scaled by SCALE2)
__device__ __half g_qh_hi[(size_t)B_*H_*S_*DK_];
__device__ __half g_qh_lo[(size_t)B_*H_*S_*DK_];

// Mask compaction + compacted K/V (written directly by proj)
__device__ int    g_idx[B_][S_];
__device__ int    g_cnt[B_];
__device__ __half g_kc[(size_t)B_*H_*S_*DK_];
__device__ __half g_vc[(size_t)B_*H_*S_*DV_];

// ---------------------------------------------------------------------------
// primitives
// ---------------------------------------------------------------------------
__device__ __forceinline__ uint32_t smaddr(const void* p) {
    return (uint32_t)__cvta_generic_to_shared(p);
}
__device__ __forceinline__ void ldsm_x4(uint32_t (&r)[4], uint32_t a) {
    asm volatile("ldmatrix.sync.aligned.m8n8.x4.shared.b16 {%0,%1,%2,%3}, [%4];"
                 : "=r"(r[0]), "=r"(r[1]), "=r"(r[2]), "=r"(r[3]) : "r"(a));
}
__device__ __forceinline__ void ldsm_x4_t(uint32_t (&r)[4], uint32_t a) {
    asm volatile("ldmatrix.sync.aligned.m8n8.x4.trans.shared.b16 {%0,%1,%2,%3}, [%4];"
                 : "=r"(r[0]), "=r"(r[1]), "=r"(r[2]), "=r"(r[3]) : "r"(a));
}
__device__ __forceinline__ void mma16816(float (&c)[4], const uint32_t (&a)[4],
                                         uint32_t b0, uint32_t b1) {
    asm volatile(
        "mma.sync.aligned.m16n8k16.row.col.f32.f16.f16.f32 "
        "{%0,%1,%2,%3}, {%4,%5,%6,%7}, {%8,%9}, {%0,%1,%2,%3};"
        : "+f"(c[0]), "+f"(c[1]), "+f"(c[2]), "+f"(c[3])
        : "r"(a[0]), "r"(a[1]), "r"(a[2]), "r"(a[3]), "r"(b0), "r"(b1));
}
__device__ __forceinline__ uint32_t packh2(float x, float y) {
    __half2 h = __floats2half2_rn(x, y);
    return *reinterpret_cast<uint32_t*>(&h);
}
__device__ __forceinline__ float ex2f(float x) {
    float y; asm("ex2.approx.ftz.f32 %0, %1;" : "=f"(y) : "f"(x)); return y;
}
__device__ __forceinline__ uint32_t ex2h2(float a, float b) {
    uint32_t h = packh2(a, b);
    uint32_t r; asm("ex2.approx.f16x2 %0, %1;" : "=r"(r) : "r"(h)); return r;
}
#define CP16(dst, src) asm volatile("cp.async.cg.shared.global [%0], [%1], 16;\n" :: "r"(dst), "l"(src))
#define CPC()          asm volatile("cp.async.commit_group;\n")
#define CPW(n)         asm volatile("cp.async.wait_group %0;\n" :: "n"(n))

// ---------------------------------------------------------------------------
// Kernel 0a/0b: pre-split fp32 -> (hi, lo) fp16
// ---------------------------------------------------------------------------
__global__ void split_a(const float* __restrict__ q, const float* __restrict__ k,
                        const float* __restrict__ v)
{
    const int z = blockIdx.y;
    const float* src = (z == 0) ? q : (z == 1) ? k : v;
    __half* hi = g_ah[z];
    __half* lo = (z < 2) ? g_al[z] : nullptr;
    size_t i = (size_t)blockIdx.x * blockDim.x + threadIdx.x;
    float4 vv = ((const float4*)src)[i];
    float f[4] = {vv.x, vv.y, vv.z, vv.w};
    __half h[4], l[4];
    #pragma unroll
    for (int e = 0; e < 4; e++) {
        h[e] = __float2half_rn(f[e]);
        l[e] = __float2half_rn(f[e] - __half2float(h[e]));
    }
    uint2 ph, pl;
    ph.x = (uint32_t)__half_as_ushort(h[0]) | ((uint32_t)__half_as_ushort(h[1]) << 16);
    ph.y = (uint32_t)__half_as_ushort(h[2]) | ((uint32_t)__half_as_ushort(h[3]) << 16);
    pl.x = (uint32_t)__half_as_ushort(l[0]) | ((uint32_t)__half_as_ushort(l[1]) << 16);
    pl.y = (uint32_t)__half_as_ushort(l[2]) | ((uint32_t)__half_as_ushort(l[3]) << 16);
    ((uint2*)hi)[i] = ph;
    if (lo) ((uint2*)lo)[i] = pl;
}
__global__ void split_w(const float* __restrict__ wq, const float* __restrict__ wk,
                        const float* __restrict__ wv)
{
    const int z = blockIdx.y;
    const float* src = (z == 0) ? wq : (z == 1) ? wk : wv;
    __half* hi = g_wh[z];
    __half* lo = (z < 2) ? g_wl[z] : nullptr;
    size_t i = (size_t)blockIdx.x * blockDim.x + threadIdx.x;
    float4 vv = ((const float4*)src)[i];
    float f[4] = {vv.x, vv.y, vv.z, vv.w};
    __half h[4], l[4];
    #pragma unroll
    for (int e = 0; e < 4; e++) {
        h[e] = __float2half_rn(f[e]);
        l[e] = __float2half_rn(f[e] - __half2float(h[e]));
    }
    uint2 ph, pl;
    ph.x = (uint32_t)__half_as_ushort(h[0]) | ((uint32_t)__half_as_ushort(h[1]) << 16);
    ph.y = (uint32_t)__half_as_ushort(h[2]) | ((uint32_t)__half_as_ushort(h[3]) << 16);
    pl.x = (uint32_t)__half_as_ushort(l[0]) | ((uint32_t)__half_as_ushort(l[1]) << 16);
    pl.y = (uint32_t)__half_as_ushort(l[2]) | ((uint32_t)__half_as_ushort(l[3]) << 16);
    ((uint2*)hi)[i] = ph;
    if (lo) ((uint2*)lo)[i] = pl;
}

// ---------------------------------------------------------------------------
// Kernel 0c: mask scan — per-batch index list of unmasked positions,
// padded with index 0 all the way to S_ (proj gathers may touch any j < S_).
// ---------------------------------------------------------------------------
__global__ void mask_scan(const int* __restrict__ mask)
{
    const int bw   = threadIdx.x >> 5;
    const int lane = threadIdx.x & 31;
    const int* mrow = mask + (size_t)bw * S_;
    int running = 0;
    for (int s0 = 0; s0 < S_; s0 += 32) {
        int m = mrow[s0 + lane];
        unsigned bal = __ballot_sync(0xffffffffu, m != 0);
        int pre = __popc(bal & ((1u << lane) - 1u));
        if (m != 0) g_idx[bw][running + pre] = s0 + lane;
        running += __popc(bal);
    }
    if (lane == 0) g_cnt[bw] = running;
    for (int j = running + lane; j < S_; j += 32) g_idx[bw][j] = 0;
}

// ---------------------------------------------------------------------------
// Kernel 1: projection GEMM (256 thr, 128x128 tile, 2 CTAs/SM).
// z=0: Q, all rows, 3 products, hi/lo output (pre-scaled by SCALE2).
// z=1: K, COMPACTED rows (gathered via g_idx), 3 products, hi output -> g_kc.
// z=2: V, COMPACTED rows, 1 product -> g_vc.
// CTAs past the compacted count exit immediately.
// ---------------------------------------------------------------------------
struct ProjSmem {
    __half Ah[2][128][40];
    __half Al[2][128][40];
    __half Wh[2][32][136];
    __half Wl[2][32][136];
};

__global__ __launch_bounds__(256, 2) void proj_mma(
    const float* __restrict__ bq, const float* __restrict__ bk, const float* __restrict__ bv)
{
    const int z = blockIdx.z;

    int bb = 0, j0 = 0, m_blk = 0;
    if (z == 0) {
        m_blk = blockIdx.y * 128;
    } else {
        bb = blockIdx.y >> 4;
        j0 = (blockIdx.y & 15) * 128;
        int npad = (g_cnt[bb] + 63) & ~63;
        if (j0 >= npad) return;            // whole chunk is past compacted range
    }

    extern __shared__ char smraw[];
    ProjSmem& S = *reinterpret_cast<ProjSmem*>(smraw);

    const __half* Agh = g_ah[z];
    const __half* Agl = (z < 2) ? g_al[z] : g_ah[z];
    const __half* Wgh = g_wh[z];
    const __half* Wgl = (z < 2) ? g_wl[z] : g_wh[z];
    const float* bias = (z == 0) ? bq : (z == 1) ? bk : bv;

    const int tid  = threadIdx.x;
    const int lane = tid & 31;
    const int warp = tid >> 5;
    const int wr = warp >> 1, wc = warp & 1;
    const int n_blk = blockIdx.x * 128;

    // Per-thread gathered A-row (one row per thread's two chunks)
    const int  ar   = tid >> 1;                     // 0..127
    size_t arow_off;
    if (z == 0) arow_off = (size_t)(m_blk + ar) * DM;
    else        arow_off = ((size_t)bb * S_ + g_idx[bb][j0 + ar]) * DM;

    float acc[2][8][4];
    #pragma unroll
    for (int mt = 0; mt < 2; mt++)
        #pragma unroll
        for (int nt = 0; nt < 8; nt++)
            #pragma unroll
            for (int e = 0; e < 4; e++) acc[mt][nt][e] = 0.0f;

    auto load_tile = [&](int kt, int buf) {
        const int k0 = kt * 32;
        // A: 128 rows x 32 cols; thread -> 1 row, 2 16B chunks
        #pragma unroll
        for (int i = 0; i < 2; i++) {
            int ac = ((tid & 1) * 2 + i) * 8;       // 0,8 or 16,24
            size_t aoff = arow_off + k0 + ac;
            CP16(smaddr(&S.Ah[buf][ar][ac]), Agh + aoff);
            if (z < 2) CP16(smaddr(&S.Al[buf][ar][ac]), Agl + aoff);
        }
        // W: 32 rows x 128 cols; 512 chunks / 256 thr
        #pragma unroll
        for (int i = 0; i < 2; i++) {
            int idx = tid * 2 + i;
            int wrow = idx >> 4, wcol = (idx & 15) * 8;
            size_t woff = (size_t)(k0 + wrow) * DM + n_blk + wcol;
            CP16(smaddr(&S.Wh[buf][wrow][wcol]), Wgh + woff);
            if (z < 2) CP16(smaddr(&S.Wl[buf][wrow][wcol]), Wgl + woff);
        }
        CPC();
    };

    load_tile(0, 0);

    for (int kt = 0; kt < DM / 32; kt++) {
        const int buf = kt & 1;
        CPW(0);
        __syncthreads();
        if (kt + 1 < DM / 32) load_tile(kt + 1, buf ^ 1);

        #pragma unroll
        for (int kc = 0; kc < 2; kc++) {
            uint32_t afh[2][4], afl[2][4];
            #pragma unroll
            for (int mt = 0; mt < 2; mt++) {
                int row = wr * 32 + mt * 16 + (lane & 15);
                int col = kc * 16 + (lane >> 4) * 8;
                ldsm_x4(afh[mt], smaddr(&S.Ah[buf][row][col]));
                if (z < 2) ldsm_x4(afl[mt], smaddr(&S.Al[buf][row][col]));
            }
            #pragma unroll
            for (int ntp = 0; ntp < 4; ntp++) {
                uint32_t bh[4], bl[4];
                int krow = kc * 16 + (lane & 15);
                int ncol = wc * 64 + ntp * 16 + (lane >> 4) * 8;
                ldsm_x4_t(bh, smaddr(&S.Wh[buf][krow][ncol]));
                if (z < 2) ldsm_x4_t(bl, smaddr(&S.Wl[buf][krow][ncol]));
                #pragma unroll
                for (int mt = 0; mt < 2; mt++) {
                    mma16816(acc[mt][2*ntp],   afh[mt], bh[0], bh[1]);
                    mma16816(acc[mt][2*ntp+1], afh[mt], bh[2], bh[3]);
                    if (z < 2) {
                        mma16816(acc[mt][2*ntp],   afh[mt], bl[0], bl[1]);
                        mma16816(acc[mt][2*ntp],   afl[mt], bh[0], bh[1]);
                        mma16816(acc[mt][2*ntp+1], afh[mt], bl[2], bl[3]);
                        mma16816(acc[mt][2*ntp+1], afl[mt], bh[2], bh[3]);
                    }
                }
            }
        }
    }

    // Epilogue
    #pragma unroll
    for (int mt = 0; mt < 2; mt++) {
        #pragma unroll
        for (int nt = 0; nt < 8; nt++) {
            int c = n_blk + wc * 64 + nt * 8 + 2 * (lane & 3);
            float b0 = bias[c], b1 = bias[c + 1];
            int hh = c >> 6, dd = c & 63;
            #pragma unroll
            for (int hf = 0; hf < 2; hf++) {
                int rl = wr * 32 + mt * 16 + (lane >> 2) + hf * 8;   // 0..127
                float v0 = acc[mt][nt][hf * 2 + 0] + b0;
                float v1 = acc[mt][nt][hf * 2 + 1] + b1;
                if (z == 0) {
                    int rg = m_blk + rl;
                    int batch = rg >> 11, s = rg & 2047;
                    size_t idx = (((size_t)batch * H_ + hh) * S_ + s) * 64 + dd;
                    v0 *= SCALE2; v1 *= SCALE2;
                    __half h0 = __float2half_rn(v0), h1 = __float2half_rn(v1);
                    __half l0 = __float2half_rn(v0 - __half2float(h0));
                    __half l1 = __float2half_rn(v1 - __half2float(h1));
                    *(__half2*)&g_qh_hi[idx] = __halves2half2(h0, h1);
                    *(__half2*)&g_qh_lo[idx] = __halves2half2(l0, l1);
                } else {
                    int j = j0 + rl;                               // compacted row
                    size_t idx = (((size_t)bb * H_ + hh) * S_ + j) * 64 + dd;
                    if (z == 1) *(__half2*)&g_kc[idx] = __floats2half2_rn(v0, v1);
                    else        *(__half2*)&g_vc[idx] = __floats2half2_rn(v0, v1);
                }
            }
        }
    }
}

// ---------------------------------------------------------------------------
// Kernel 2: flash attention over COMPACTED keys (unchanged from R8).
// ---------------------------------------------------------------------------
constexpr int KH_OFF = 0;
constexpr int VT_OFF = 18432;
constexpr int QH_OFF = 0;
constexpr int QL_OFF = 18432;
constexpr int ATTN_SMEM = 36864;
constexpr int TSTRIDE = 4608;

__global__ __launch_bounds__(256, 2) void attn_mma(
    const float* __restrict__ qin,
    float*       __restrict__ out)
{
    extern __shared__ char smraw[];
    __half* Kh = (__half*)(smraw + KH_OFF);
    __half* Vt = (__half*)(smraw + VT_OFF);
    __half* Qh = (__half*)(smraw + QH_OFF);
    __half* Ql = (__half*)(smraw + QL_OFF);

    const int tid  = threadIdx.x;
    const int lane = tid & 31;
    const int warp = tid >> 5;
    const int b  = blockIdx.z;
    const int h  = blockIdx.y;
    const int q0 = blockIdx.x * 128;

    const size_t head = ((size_t)b * H_ + h) * S_ * 64;
    const int n_cnt = g_cnt[b];
    const int ntile = (n_cnt + 63) >> 6;
    const uint32_t ONESF = 0x3C003C00u;

    auto load_tile = [&](int kt, int buf) {
        const int kb = kt * 64;
        #pragma unroll
        for (int i = 0; i < 2; i++) {
            int idx = tid * 2 + i;
            int r = idx >> 3, c = (idx & 7) * 8;
            size_t g = head + (size_t)(kb + r) * 64 + c;
            CP16(smaddr(Kh + buf * TSTRIDE + r * 72 + c), g_kc + g);
            CP16(smaddr(Vt + buf * TSTRIDE + r * 72 + c), g_vc + g);
        }
        CPC();
    };

    for (int i = tid; i < 1024; i += 256) {
        int r = i >> 3, c = (i & 7) * 8;
        size_t g = head + (size_t)(q0 + r) * 64 + c;
        CP16(smaddr(Qh + r * 72 + c), g_qh_hi + g);
        CP16(smaddr(Ql + r * 72 + c), g_qh_lo + g);
    }
    CPC(); CPW(0);
    __syncthreads();

    uint32_t qfh[4][4], qfl[4][4];
    const int m0 = warp * 16;
    #pragma unroll
    for (int kc = 0; kc < 4; kc++) {
        int row = m0 + (lane & 15);
        int col = kc * 16 + (lane >> 4) * 8;
        ldsm_x4(qfh[kc], smaddr(Qh + row * 72 + col));
        ldsm_x4(qfl[kc], smaddr(Ql + row * 72 + col));
    }
    __syncthreads();
    load_tile(0, 0);

    float m_i[2] = {-3.0e38f, -3.0e38f};
    float o[9][4];
    #pragma unroll
    for (int nt = 0; nt < 9; nt++)
        #pragma unroll
        for (int e = 0; e < 4; e++) o[nt][e] = 0.0f;

    for (int kt = 0; kt < ntile; kt++) {
        const int buf = kt & 1;
        CPW(0);
        __syncthreads();
        if (kt + 1 < ntile) load_tile(kt + 1, buf ^ 1);

        float s[8][4];
        #pragma unroll
        for (int nt = 0; nt < 8; nt++)
            #pragma unroll
            for (int e = 0; e < 4; e++) s[nt][e] = 0.0f;

        #pragma unroll
        for (int kc = 0; kc < 4; kc++) {
            #pragma unroll
            for (int g = 0; g < 2; g++) {
                uint32_t bh[2][4];
                #pragma unroll
                for (int j = 0; j < 2; j++) {
                    int ntp = g * 2 + j;
                    int row = ntp * 16 + (lane >> 4) * 8 + (lane & 7);
                    int col = kc * 16 + ((lane >> 3) & 1) * 8;
                    ldsm_x4(bh[j], smaddr(Kh + buf * TSTRIDE + row * 72 + col));
                }
                #pragma unroll
                for (int j = 0; j < 2; j++) {
                    int ntp = g * 2 + j;
                    mma16816(s[2*ntp],   qfh[kc], bh[j][0], bh[j][1]);
                    mma16816(s[2*ntp],   qfl[kc], bh[j][0], bh[j][1]);
                    mma16816(s[2*ntp+1], qfh[kc], bh[j][2], bh[j][3]);
                    mma16816(s[2*ntp+1], qfl[kc], bh[j][2], bh[j][3]);
                }
            }
        }

        const int cbase = kt * 64 + 2 * (lane & 3);
        #pragma unroll
        for (int nt = 0; nt < 8; nt++) {
            int c0 = cbase + nt * 8;
            if (c0 >= n_cnt)     { s[nt][0] = NEG; s[nt][2] = NEG; }
            if (c0 + 1 >= n_cnt) { s[nt][1] = NEG; s[nt][3] = NEG; }
        }

        float mx0 = -3.0e38f, mx1 = -3.0e38f;
        #pragma unroll
        for (int nt = 0; nt < 8; nt++) {
            mx0 = fmaxf(mx0, fmaxf(s[nt][0], s[nt][1]));
            mx1 = fmaxf(mx1, fmaxf(s[nt][2], s[nt][3]));
        }
        mx0 = fmaxf(mx0, __shfl_xor_sync(0xffffffffu, mx0, 1));
        mx0 = fmaxf(mx0, __shfl_xor_sync(0xffffffffu, mx0, 2));
        mx1 = fmaxf(mx1, __shfl_xor_sync(0xffffffffu, mx1, 1));
        mx1 = fmaxf(mx1, __shfl_xor_sync(0xffffffffu, mx1, 2));
        float mn0 = fmaxf(fmaxf(m_i[0], mx0), -1.0e8f);
        float mn1 = fmaxf(fmaxf(m_i[1], mx1), -1.0e8f);
        float sc0 = ex2f(m_i[0] - mn0), sc1 = ex2f(m_i[1] - mn1);
        m_i[0] = mn0; m_i[1] = mn1;

        uint32_t p[8][2];
        #pragma unroll
        for (int nt = 0; nt < 8; nt++) {
            p[nt][0] = ex2h2(s[nt][0] - mn0, s[nt][1] - mn0);
            p[nt][1] = ex2h2(s[nt][2] - mn1, s[nt][3] - mn1);
        }

        #pragma unroll
        for (int nt = 0; nt < 9; nt++) {
            o[nt][0] *= sc0; o[nt][1] *= sc0;
            o[nt][2] *= sc1; o[nt][3] *= sc1;
        }

        #pragma unroll
        for (int kc = 0; kc < 4; kc++) {
            uint32_t a[4] = { p[2*kc][0], p[2*kc][1], p[2*kc+1][0], p[2*kc+1][1] };
            #pragma unroll
            for (int g = 0; g < 2; g++) {
                uint32_t bv[2][4];
                #pragma unroll
                for (int j = 0; j < 2; j++) {
                    int ntp = g * 2 + j;
                    int row = kc * 16 + (lane & 15);
                    int col = ntp * 16 + (lane >> 4) * 8;
                    ldsm_x4_t(bv[j], smaddr(Vt + buf * TSTRIDE + row * 72 + col));
                }
                #pragma unroll
                for (int j = 0; j < 2; j++) {
                    int ntp = g * 2 + j;
                    mma16816(o[2*ntp],   a, bv[j][0], bv[j][1]);
                    mma16816(o[2*ntp+1], a, bv[j][2], bv[j][3]);
                }
            }
            mma16816(o[8], a, ONESF, ONESF);
        }
    }

    float inv0 = 1.0f / o[8][0], inv1 = 1.0f / o[8][2];
    int r0 = q0 + warp * 16 + (lane >> 2);
    int r1 = r0 + 8;
    #pragma unroll
    for (int nt = 0; nt < 8; nt++) {
        int c = h * 64 + nt * 8 + 2 * (lane & 3);
        size_t i0 = ((size_t)b * S_ + r0) * (H_ * DV_) + c;
        size_t i1 = ((size_t)b * S_ + r1) * (H_ * DV_) + c;
        float2 q0v = *(const float2*)(qin + i0);
        float2 q1v = *(const float2*)(qin + i1);
        float2 o0, o1;
        o0.x = o[nt][0] * inv0 + q0v.x;
        o0.y = o[nt][1] * inv0 + q0v.y;
        o1.x = o[nt][2] * inv1 + q1v.x;
        o1.y = o[nt][3] * inv1 + q1v.y;
        *(float2*)(out + i0) = o0;
        *(float2*)(out + i1) = o1;
    }
}

extern "C" void kernel_launch(void* const* d_in, const int* in_sizes, int n_in,
                              void* d_out, int out_size)
{
    (void)in_sizes; (void)n_in; (void)out_size;
    const float* q    = (const float*)d_in[0];
    const float* k    = (const float*)d_in[1];
    const float* v    = (const float*)d_in[2];
    const int*   mask = (const int*)  d_in[3];
    const float* wq   = (const float*)d_in[4];
    const float* bq   = (const float*)d_in[5];
    const float* wk   = (const float*)d_in[6];
    const float* bk   = (const float*)d_in[7];
    const float* wv   = (const float*)d_in[8];
    const float* bv   = (const float*)d_in[9];
    float* out = (float*)d_out;

    static bool attr_set = false;
    if (!attr_set) {
        cudaFuncSetAttribute(proj_mma, cudaFuncAttributeMaxDynamicSharedMemorySize,
                             (int)sizeof(ProjSmem));
        attr_set = true;
    }

    dim3 sag((ROWS * DM / 4) / 256, 3);
    split_a<<<sag, 256>>>(q, k, v);
    dim3 swg((DM * DM / 4) / 256, 3);
    split_w<<<swg, 256>>>(wq, wk, wv);
    mask_scan<<<1, 128>>>(mask);

    dim3 pg(DM / 128, ROWS / 128, 3);     // (8, 64, 3); z>0 CTAs early-exit past count
    proj_mma<<<pg, 256, sizeof(ProjSmem)>>>(bq, bk, bv);

    dim3 ag(S_ / 128, H_, B_);
    attn_mma<<<ag, 256, ATTN_SMEM>>>(q, out);
}